// round 5
// baseline (speedup 1.0000x reference)
#include <cuda_runtime.h>
#include <cstdint>

// Problem dims (fixed by weights): D=128, H=4, C=32, OUT=64. N,E taken from in_sizes.
#define MAXN 50048
#define MAXETOT 850048   // E + N self loops

// ---------------- scratch (device globals; allocation-free) ----------------
__device__ __align__(16) float    g_xl   [(size_t)MAXN * 128];   // projected features
__device__ __align__(16) float    g_accum[(size_t)MAXN * 128];   // weighted-sum accum / h0 / h1
__device__ __align__(16) float    g_alpha[(size_t)MAXETOT * 4];  // per-edge logits
__device__ __align__(16) float    g_as   [(size_t)MAXN * 4];
__device__ __align__(16) float    g_ad   [(size_t)MAXN * 4];
__device__ __align__(16) unsigned g_amax [(size_t)MAXN * 4];     // monotone-encoded float max
__device__ __align__(16) float    g_denom[(size_t)MAXN * 4];

// ---------------- helpers ----------------
__device__ __forceinline__ unsigned encf(float f) {
    unsigned u = __float_as_uint(f);
    return (u & 0x80000000u) ? ~u : (u | 0x80000000u);
}
__device__ __forceinline__ float decf(unsigned u) {
    return (u & 0x80000000u) ? __uint_as_float(u & 0x7fffffffu) : __uint_as_float(~u);
}
__device__ __forceinline__ float lrelu(float x) { return x > 0.f ? x : 0.2f * x; }

__device__ __forceinline__ void red_add_v4(float* p, float a, float b, float c, float d) {
    asm volatile("red.global.add.v4.f32 [%0], {%1,%2,%3,%4};"
                 :: "l"(p), "f"(a), "f"(b), "f"(c), "f"(d) : "memory");
}

// ---------------- zero scratch ----------------
__global__ void k_zero(float* __restrict__ acc, int n128,
                       float* __restrict__ den, unsigned* __restrict__ amx, int nsmall) {
    int i = blockIdx.x * blockDim.x + threadIdx.x;
    if (i < n128) acc[i] = 0.f;
    if (i < nsmall) { den[i] = 0.f; amx[i] = 0u; }  // 0u < encf(any float) — identity
}

// ---------------- SGEMM: C[n,M] = A[n,128] @ W[128,M] (+bias). BM=BN=64, BK=16, 4x4/thread ----------------
__global__ void k_gemm128(const float* __restrict__ A, const float* __restrict__ W,
                          const float* __restrict__ bias, float* __restrict__ C,
                          int n, int M) {
    __shared__ __align__(16) float As[16][68];
    __shared__ __align__(16) float Ws[16][68];
    const int tid = threadIdx.x;           // 256
    const int tx = tid & 15, ty = tid >> 4;
    const int rowBase = blockIdx.y * 64;
    const int colBase = blockIdx.x * 64;
    float acc[4][4] = {};

    for (int kt = 0; kt < 128; kt += 16) {
        {   // A tile
            int r = tid >> 2, kv = (tid & 3) * 4;
            int grow = rowBase + r;
            float4 v = make_float4(0.f, 0.f, 0.f, 0.f);
            if (grow < n) v = *(const float4*)&A[(size_t)grow * 128 + kt + kv];
            As[kv + 0][r] = v.x; As[kv + 1][r] = v.y;
            As[kv + 2][r] = v.z; As[kv + 3][r] = v.w;
        }
        {   // W tile
            int k = tid >> 4, cv = (tid & 15) * 4;
            float4 v = *(const float4*)&W[(size_t)(kt + k) * M + colBase + cv];
            *(float4*)&Ws[k][cv] = v;
        }
        __syncthreads();
        #pragma unroll
        for (int k = 0; k < 16; k++) {
            float4 av = *(const float4*)&As[k][ty * 4];
            float4 bv = *(const float4*)&Ws[k][tx * 4];
            float a[4] = {av.x, av.y, av.z, av.w};
            float b[4] = {bv.x, bv.y, bv.z, bv.w};
            #pragma unroll
            for (int i = 0; i < 4; i++)
                #pragma unroll
                for (int j = 0; j < 4; j++)
                    acc[i][j] = fmaf(a[i], b[j], acc[i][j]);
        }
        __syncthreads();
    }
    #pragma unroll
    for (int i = 0; i < 4; i++) {
        int row = rowBase + ty * 4 + i;
        if (row >= n) continue;
        #pragma unroll
        for (int j = 0; j < 4; j++) {
            int col = colBase + tx * 4 + j;
            float v = acc[i][j];
            if (bias) v += bias[col];
            C[(size_t)row * M + col] = v;
        }
    }
}

// ---------------- attention dot products ----------------
__global__ void k_att(const float* __restrict__ xl, const float* __restrict__ ws,
                      const float* __restrict__ wd, float* __restrict__ as_,
                      float* __restrict__ ad_, int n, int H) {
    int warp = (blockIdx.x * blockDim.x + threadIdx.x) >> 5;
    int l = threadIdx.x & 31;
    if (warp >= n) return;
    float4 xv = *(const float4*)&xl[(size_t)warp * 128 + l * 4];
    float4 sv = *(const float4*)&ws[l * 4];
    float4 dv = *(const float4*)&wd[l * 4];
    float ps = xv.x * sv.x + xv.y * sv.y + xv.z * sv.z + xv.w * sv.w;
    float pd = xv.x * dv.x + xv.y * dv.y + xv.z * dv.z + xv.w * dv.w;
    int width = 32 / H;   // lanes per head
    for (int off = width >> 1; off > 0; off >>= 1) {
        ps += __shfl_xor_sync(0xffffffffu, ps, off, width);
        pd += __shfl_xor_sync(0xffffffffu, pd, off, width);
    }
    if ((l & (width - 1)) == 0) {
        as_[warp * H + l / width] = ps;
        ad_[warp * H + l / width] = pd;
    }
}

// ---------------- edge pass A: logits + segment_max ----------------
__global__ void k_edgeA4(const int* __restrict__ src, const int* __restrict__ dst,
                         int E, int Etot, const float* __restrict__ as_,
                         const float* __restrict__ ad_, float* __restrict__ alpha,
                         unsigned* __restrict__ amx) {
    int e = blockIdx.x * blockDim.x + threadIdx.x;
    if (e >= Etot) return;
    int s, d;
    if (e < E) { s = src[e]; d = dst[e]; } else { s = e - E; d = s; }
    float4 a = *(const float4*)&as_[(size_t)s * 4];
    float4 b = *(const float4*)&ad_[(size_t)d * 4];
    float4 v;
    v.x = lrelu(a.x + b.x); v.y = lrelu(a.y + b.y);
    v.z = lrelu(a.z + b.z); v.w = lrelu(a.w + b.w);
    *(float4*)&alpha[(size_t)e * 4] = v;
    atomicMax(&amx[d * 4 + 0], encf(v.x));
    atomicMax(&amx[d * 4 + 1], encf(v.y));
    atomicMax(&amx[d * 4 + 2], encf(v.z));
    atomicMax(&amx[d * 4 + 3], encf(v.w));
}

__global__ void k_edgeA1(const int* __restrict__ src, const int* __restrict__ dst,
                         int E, int Etot, const float* __restrict__ as_,
                         const float* __restrict__ ad_, float* __restrict__ alpha,
                         unsigned* __restrict__ amx) {
    int e = blockIdx.x * blockDim.x + threadIdx.x;
    if (e >= Etot) return;
    int s, d;
    if (e < E) { s = src[e]; d = dst[e]; } else { s = e - E; d = s; }
    float v = lrelu(as_[s] + ad_[d]);
    alpha[e] = v;
    atomicMax(&amx[d], encf(v));
}

// ---------------- edge pass B: ex = exp(alpha - amax); denom += ex; accum += ex * xl[src] ----------------
// one warp per edge; lane l handles channels 4l..4l+3 (head = l>>3 for H=4)
__global__ void k_edgeB4(const int* __restrict__ src, const int* __restrict__ dst,
                         int E, int Etot, const float* __restrict__ alpha,
                         const unsigned* __restrict__ amx, float* __restrict__ denom,
                         const float* __restrict__ xl, float* __restrict__ accum) {
    int e = (blockIdx.x * blockDim.x + threadIdx.x) >> 5;
    int l = threadIdx.x & 31;
    if (e >= Etot) return;
    int s, d;
    if (e < E) { s = src[e]; d = dst[e]; } else { s = e - E; d = s; }
    float exv = 0.f;
    if (l < 4) {
        exv = __expf(alpha[(size_t)e * 4 + l] - decf(amx[d * 4 + l]));
        atomicAdd(&denom[d * 4 + l], exv);
    }
    float exh = __shfl_sync(0xffffffffu, exv, l >> 3);
    float4 xv = *(const float4*)&xl[(size_t)s * 128 + l * 4];
    red_add_v4(&accum[(size_t)d * 128 + l * 4],
               xv.x * exh, xv.y * exh, xv.z * exh, xv.w * exh);
}

__global__ void k_edgeB1(const int* __restrict__ src, const int* __restrict__ dst,
                         int E, int Etot, const float* __restrict__ alpha,
                         const unsigned* __restrict__ amx, float* __restrict__ denom,
                         const float* __restrict__ xl, float* __restrict__ accum) {
    int e = (blockIdx.x * blockDim.x + threadIdx.x) >> 5;
    int l = threadIdx.x & 31;
    if (e >= Etot) return;
    int s, d;
    if (e < E) { s = src[e]; d = dst[e]; } else { s = e - E; d = s; }
    float exv = 0.f;
    if (l == 0) {
        exv = __expf(alpha[e] - decf(amx[d]));
        atomicAdd(&denom[d], exv);
    }
    float exh = __shfl_sync(0xffffffffu, exv, 0);
    float4 xv = *(const float4*)&xl[(size_t)s * 128 + l * 4];
    red_add_v4(&accum[(size_t)d * 128 + l * 4],
               xv.x * exh, xv.y * exh, xv.z * exh, xv.w * exh);
}

// ---------------- per-node finalize: h = relu(accum/denom + bias) (in place) ----------------
__global__ void k_fin4(float* __restrict__ accum, const float* __restrict__ denom,
                       const float* __restrict__ bias, int n) {
    int i = blockIdx.x * blockDim.x + threadIdx.x;     // float4 units
    if (i >= n * 32) return;
    int node = i >> 5, t4 = i & 31, head = t4 >> 3;
    float inv = 1.f / (denom[node * 4 + head] + 1e-16f);
    float4 v = *(float4*)&accum[(size_t)i * 4];
    float4 b = *(const float4*)&bias[t4 * 4];
    v.x = fmaxf(v.x * inv + b.x, 0.f);
    v.y = fmaxf(v.y * inv + b.y, 0.f);
    v.z = fmaxf(v.z * inv + b.z, 0.f);
    v.w = fmaxf(v.w * inv + b.w, 0.f);
    *(float4*)&accum[(size_t)i * 4] = v;
}

__global__ void k_fin1(float* __restrict__ accum, const float* __restrict__ denom,
                       const float* __restrict__ bias, int n) {
    int i = blockIdx.x * blockDim.x + threadIdx.x;
    if (i >= n * 32) return;
    int node = i >> 5, t4 = i & 31;
    float inv = 1.f / (denom[node] + 1e-16f);
    float4 v = *(float4*)&accum[(size_t)i * 4];
    float4 b = *(const float4*)&bias[t4 * 4];
    v.x = fmaxf(v.x * inv + b.x, 0.f);
    v.y = fmaxf(v.y * inv + b.y, 0.f);
    v.z = fmaxf(v.z * inv + b.z, 0.f);
    v.w = fmaxf(v.w * inv + b.w, 0.f);
    *(float4*)&accum[(size_t)i * 4] = v;
}

// ---------------- launch ----------------
extern "C" void kernel_launch(void* const* d_in, const int* in_sizes, int n_in,
                              void* d_out, int out_size) {
    const float* x    = (const float*)d_in[0];
    const int*   ei   = (const int*)d_in[1];    // int32! (JAX default x64-disabled)
    const float* W0   = (const float*)d_in[2];
    const float* as0w = (const float*)d_in[3];
    const float* ad0w = (const float*)d_in[4];
    const float* b0   = (const float*)d_in[5];
    const float* W1   = (const float*)d_in[6];
    const float* as1w = (const float*)d_in[7];
    const float* ad1w = (const float*)d_in[8];
    const float* b1   = (const float*)d_in[9];
    const float* Wn   = (const float*)d_in[10];
    const float* bn   = (const float*)d_in[11];
    const float* We   = (const float*)d_in[12];
    const float* be   = (const float*)d_in[13];
    float* out = (float*)d_out;

    const int n    = in_sizes[0] / 128;
    const int E    = in_sizes[1] / 2;
    const int Etot = E + n;
    const int* src = ei;
    const int* dst = ei + E;

    float *xl, *accum, *alpha, *as_, *ad_, *denom;
    unsigned* amx;
    cudaGetSymbolAddress((void**)&xl,    g_xl);
    cudaGetSymbolAddress((void**)&accum, g_accum);
    cudaGetSymbolAddress((void**)&alpha, g_alpha);
    cudaGetSymbolAddress((void**)&as_,   g_as);
    cudaGetSymbolAddress((void**)&ad_,   g_ad);
    cudaGetSymbolAddress((void**)&amx,   g_amax);
    cudaGetSymbolAddress((void**)&denom, g_denom);

    const int T = 256;
    dim3 gemmGrid128(2, (n + 63) / 64);
    dim3 gemmGrid64(1, (n + 63) / 64);
    int zeroBlocks = (n * 128 + T - 1) / T;
    int attBlocks  = (n + 7) / 8;
    int eABlocks   = (Etot + T - 1) / T;
    int eBBlocks   = (Etot + 7) / 8;       // 8 warps (edges) per 256-thread block
    int finBlocks  = (n * 32 + T - 1) / T;

    // ---- layer 0 (H=4, C=32) ----
    k_zero<<<zeroBlocks, T>>>(accum, n * 128, denom, amx, n * 4);
    k_gemm128<<<gemmGrid128, T>>>(x, W0, nullptr, xl, n, 128);
    k_att<<<attBlocks, T>>>(xl, as0w, ad0w, as_, ad_, n, 4);
    k_edgeA4<<<eABlocks, T>>>(src, dst, E, Etot, as_, ad_, alpha, amx);
    k_edgeB4<<<eBBlocks, T>>>(src, dst, E, Etot, alpha, amx, denom, xl, accum);
    k_fin4<<<finBlocks, T>>>(accum, denom, b0, n);     // accum := h0

    // ---- layer 1 (H=1, C=128) ----
    k_gemm128<<<gemmGrid128, T>>>(accum, W1, nullptr, xl, n, 128);   // xl := h0 @ W1
    k_zero<<<zeroBlocks, T>>>(accum, n * 128, denom, amx, n);
    k_att<<<attBlocks, T>>>(xl, as1w, ad1w, as_, ad_, n, 1);
    k_edgeA1<<<eABlocks, T>>>(src, dst, E, Etot, as_, ad_, alpha, amx);
    k_edgeB1<<<eBBlocks, T>>>(src, dst, E, Etot, alpha, amx, denom, xl, accum);
    k_fin1<<<finBlocks, T>>>(accum, denom, b1, n);     // accum := h1

    // ---- projections ----
    k_gemm128<<<gemmGrid64, T>>>(x,     We, be, out,                  n, 64);  // h_ego
    k_gemm128<<<gemmGrid64, T>>>(accum, Wn, bn, out + (size_t)n * 64, n, 64);  // h_neighbor
}

// round 8
// speedup vs baseline: 1.9453x; 1.9453x over previous
#include <cuda_runtime.h>
#include <cstdint>

// Fixed dims: D=128, H=4, C=32, OUT=64. N,E from in_sizes.
#define MAXN 50048
#define MAXETOT 850048   // E + N self loops

// ---------------- scratch (device globals; allocation-free) ----------------
__device__ __align__(16) float g_xl   [(size_t)MAXN * 128];   // projected features
__device__ __align__(16) float g_accum[(size_t)MAXN * 128];   // layer output h0 / h1
__device__ __align__(16) float g_as   [(size_t)MAXN * 4];
__device__ __align__(16) float g_ad   [(size_t)MAXN * 4];
__device__ int g_deg   [MAXN];
__device__ int g_rowptr[MAXN + 1];
__device__ int g_cursor[MAXN];
__device__ int g_csrc  [MAXETOT];

__device__ __forceinline__ float lrelu(float x) { return x > 0.f ? x : 0.2f * x; }

// ================= CSR build (once per call; edge structure shared by both layers) =================
__global__ void k_initdeg(int* __restrict__ deg, int n) {
    int i = blockIdx.x * blockDim.x + threadIdx.x;
    if (i < n) deg[i] = 1;   // self loop
}
__global__ void k_count(const int* __restrict__ dst, int E, int* __restrict__ deg) {
    int e = blockIdx.x * blockDim.x + threadIdx.x;
    if (e < E) atomicAdd(&deg[dst[e]], 1);
}
// single-block exclusive scan of deg[0..n) -> rowptr, cursor; rowptr[n] = total
__global__ void k_scan(const int* __restrict__ deg, int* __restrict__ rowptr,
                       int* __restrict__ cursor, int n) {
    __shared__ int sums[1024];
    int tid = threadIdx.x;                      // 1024 threads
    int chunk = (n + 1023) / 1024;
    int beg = tid * chunk;
    int end = min(beg + chunk, n);
    int s = 0;
    for (int i = beg; i < end; i++) s += deg[i];
    sums[tid] = s;
    __syncthreads();
    for (int off = 1; off < 1024; off <<= 1) {  // Hillis-Steele inclusive scan
        int v = (tid >= off) ? sums[tid - off] : 0;
        __syncthreads();
        sums[tid] += v;
        __syncthreads();
    }
    int run = (tid == 0) ? 0 : sums[tid - 1];   // exclusive offset
    for (int i = beg; i < end; i++) {
        rowptr[i] = run;
        cursor[i] = run;
        run += deg[i];
    }
    if (end == n) rowptr[n] = run;              // run == grand total
}
__global__ void k_fill(const int* __restrict__ src, const int* __restrict__ dst,
                       int E, int Etot, int* __restrict__ cursor, int* __restrict__ csrc) {
    int e = blockIdx.x * blockDim.x + threadIdx.x;
    if (e >= Etot) return;
    int s, d;
    if (e < E) { s = src[e]; d = dst[e]; } else { s = e - E; d = s; }
    int p = atomicAdd(&cursor[d], 1);
    csrc[p] = s;
}

// ================= SGEMM: C[n,M] = A[n,128] @ W[128,M] (+bias). 64x64 tile, 4x4/thread ============
__global__ void __launch_bounds__(256)
k_gemm128(const float* __restrict__ A, const float* __restrict__ W,
          const float* __restrict__ bias, float* __restrict__ C,
          int n, int M) {
    __shared__ __align__(16) float As[16][68];
    __shared__ __align__(16) float Ws[16][68];
    const int tid = threadIdx.x;           // 256
    const int tx = tid & 15, ty = tid >> 4;
    const int rowBase = blockIdx.y * 64;
    const int colBase = blockIdx.x * 64;
    float acc[4][4] = {};

    for (int kt = 0; kt < 128; kt += 16) {
        {   // A tile
            int r = tid >> 2, kv = (tid & 3) * 4;
            int grow = rowBase + r;
            float4 v = make_float4(0.f, 0.f, 0.f, 0.f);
            if (grow < n) v = *(const float4*)&A[(size_t)grow * 128 + kt + kv];
            As[kv + 0][r] = v.x; As[kv + 1][r] = v.y;
            As[kv + 2][r] = v.z; As[kv + 3][r] = v.w;
        }
        {   // W tile
            int k = tid >> 4, cv = (tid & 15) * 4;
            float4 v = *(const float4*)&W[(size_t)(kt + k) * M + colBase + cv];
            *(float4*)&Ws[k][cv] = v;
        }
        __syncthreads();
        #pragma unroll
        for (int k = 0; k < 16; k++) {
            float4 av = *(const float4*)&As[k][ty * 4];
            float4 bv = *(const float4*)&Ws[k][tx * 4];
            float a[4] = {av.x, av.y, av.z, av.w};
            float b[4] = {bv.x, bv.y, bv.z, bv.w};
            #pragma unroll
            for (int i = 0; i < 4; i++)
                #pragma unroll
                for (int j = 0; j < 4; j++)
                    acc[i][j] = fmaf(a[i], b[j], acc[i][j]);
        }
        __syncthreads();
    }
    #pragma unroll
    for (int i = 0; i < 4; i++) {
        int row = rowBase + ty * 4 + i;
        if (row >= n) continue;
        #pragma unroll
        for (int j = 0; j < 4; j++) {
            int col = colBase + tx * 4 + j;
            float v = acc[i][j];
            if (bias) v += bias[col];
            C[(size_t)row * M + col] = v;
        }
    }
}

// ================= attention dot products: as[n,h] = <xl[n,h,:], att_s[h,:]> ======================
__global__ void __launch_bounds__(256)
k_att(const float* __restrict__ xl, const float* __restrict__ ws,
      const float* __restrict__ wd, float* __restrict__ as_,
      float* __restrict__ ad_, int n, int H) {
    int warp = (blockIdx.x * blockDim.x + threadIdx.x) >> 5;
    int l = threadIdx.x & 31;
    if (warp >= n) return;
    float4 xv = *(const float4*)&xl[(size_t)warp * 128 + l * 4];
    float4 sv = *(const float4*)&ws[l * 4];
    float4 dv = *(const float4*)&wd[l * 4];
    float ps = xv.x * sv.x + xv.y * sv.y + xv.z * sv.z + xv.w * sv.w;
    float pd = xv.x * dv.x + xv.y * dv.y + xv.z * dv.z + xv.w * dv.w;
    int width = 32 / H;   // lanes per head
    for (int off = width >> 1; off > 0; off >>= 1) {
        ps += __shfl_xor_sync(0xffffffffu, ps, off, width);
        pd += __shfl_xor_sync(0xffffffffu, pd, off, width);
    }
    if ((l & (width - 1)) == 0) {
        as_[warp * H + l / width] = ps;
        ad_[warp * H + l / width] = pd;
    }
}

// ================= fused GAT aggregation: warp per destination node, online softmax ===============
// lane l owns channels 4l..4l+3; head = l>>3 for H=4, 0 for H=1.
// out = relu( (sum_e ex_e * xl[src_e]) / (sum_e ex_e + 1e-16) + bias ), ex relative to running max.
template <int H>
__global__ void __launch_bounds__(256)
k_agg(const int* __restrict__ rowptr, const int* __restrict__ csrc,
      const float* __restrict__ as_, const float* __restrict__ ad_,
      const float* __restrict__ xl, const float* __restrict__ bias,
      float* __restrict__ outh, int n) {
    int d = (blockIdx.x * blockDim.x + threadIdx.x) >> 5;
    if (d >= n) return;
    int l = threadIdx.x & 31;
    const int head = (H == 4) ? (l >> 3) : 0;
    float a_d = ad_[d * H + head];
    int i = rowptr[d];
    int end = rowptr[d + 1];
    float m = -1e30f, den = 0.f;
    float4 acc = make_float4(0.f, 0.f, 0.f, 0.f);

    int s = (i < end) ? csrc[i] : 0;         // software pipeline: index one ahead
    for (; i < end; i++) {
        int sc = s;
        if (i + 1 < end) s = csrc[i + 1];
        float a = lrelu(as_[sc * H + head] + a_d);
        float4 xv = *(const float4*)&xl[(size_t)sc * 128 + l * 4];
        float nm = fmaxf(m, a);
        float rs = __expf(m - nm);           // rescale old accum (0 on first iter)
        float ex = __expf(a - nm);
        den = den * rs + ex;
        acc.x = acc.x * rs + ex * xv.x;
        acc.y = acc.y * rs + ex * xv.y;
        acc.z = acc.z * rs + ex * xv.z;
        acc.w = acc.w * rs + ex * xv.w;
        m = nm;
    }
    float inv = 1.f / (den + 1e-16f);
    float4 b = *(const float4*)&bias[l * 4];
    float4 o;
    o.x = fmaxf(acc.x * inv + b.x, 0.f);
    o.y = fmaxf(acc.y * inv + b.y, 0.f);
    o.z = fmaxf(acc.z * inv + b.z, 0.f);
    o.w = fmaxf(acc.w * inv + b.w, 0.f);
    *(float4*)&outh[(size_t)d * 128 + l * 4] = o;
}

// ================= launch =================
extern "C" void kernel_launch(void* const* d_in, const int* in_sizes, int n_in,
                              void* d_out, int out_size) {
    const float* x    = (const float*)d_in[0];
    const int*   ei   = (const int*)d_in[1];    // int32 (JAX x64 disabled)
    const float* W0   = (const float*)d_in[2];
    const float* as0w = (const float*)d_in[3];
    const float* ad0w = (const float*)d_in[4];
    const float* b0   = (const float*)d_in[5];
    const float* W1   = (const float*)d_in[6];
    const float* as1w = (const float*)d_in[7];
    const float* ad1w = (const float*)d_in[8];
    const float* b1   = (const float*)d_in[9];
    const float* Wn   = (const float*)d_in[10];
    const float* bn   = (const float*)d_in[11];
    const float* We   = (const float*)d_in[12];
    const float* be   = (const float*)d_in[13];
    float* out = (float*)d_out;

    const int n    = in_sizes[0] / 128;
    const int E    = in_sizes[1] / 2;
    const int Etot = E + n;
    const int* src = ei;
    const int* dst = ei + E;

    float *xl, *accum, *as_, *ad_;
    int *deg, *rowptr, *cursor, *csrc;
    cudaGetSymbolAddress((void**)&xl,     g_xl);
    cudaGetSymbolAddress((void**)&accum,  g_accum);
    cudaGetSymbolAddress((void**)&as_,    g_as);
    cudaGetSymbolAddress((void**)&ad_,    g_ad);
    cudaGetSymbolAddress((void**)&deg,    g_deg);
    cudaGetSymbolAddress((void**)&rowptr, g_rowptr);
    cudaGetSymbolAddress((void**)&cursor, g_cursor);
    cudaGetSymbolAddress((void**)&csrc,   g_csrc);

    const int T = 256;
    dim3 gemmGrid128(2, (n + 63) / 64);
    dim3 gemmGrid64(1, (n + 63) / 64);
    int nBlocks    = (n + T - 1) / T;
    int eBlocks    = (E + T - 1) / T;
    int etBlocks   = (Etot + T - 1) / T;
    int warpBlocks = (n + 7) / 8;       // 8 warps / 256-thread block

    // ---- CSR build (shared by both layers) ----
    k_initdeg<<<nBlocks, T>>>(deg, n);
    k_count<<<eBlocks, T>>>(dst, E, deg);
    k_scan<<<1, 1024>>>(deg, rowptr, cursor, n);
    k_fill<<<etBlocks, T>>>(src, dst, E, Etot, cursor, csrc);

    // ---- layer 0 (H=4, C=32) ----
    k_gemm128<<<gemmGrid128, T>>>(x, W0, nullptr, xl, n, 128);
    k_att<<<warpBlocks, T>>>(xl, as0w, ad0w, as_, ad_, n, 4);
    k_agg<4><<<warpBlocks, T>>>(rowptr, csrc, as_, ad_, xl, b0, accum, n);   // accum := h0

    // ---- layer 1 (H=1, C=128) ----
    k_gemm128<<<gemmGrid128, T>>>(accum, W1, nullptr, xl, n, 128);           // xl := h0 @ W1
    k_att<<<warpBlocks, T>>>(xl, as1w, ad1w, as_, ad_, n, 1);
    k_agg<1><<<warpBlocks, T>>>(rowptr, csrc, as_, ad_, xl, b1, accum, n);   // accum := h1

    // ---- projections ----
    k_gemm128<<<gemmGrid64, T>>>(x,     We, be, out,                  n, 64);  // h_ego
    k_gemm128<<<gemmGrid64, T>>>(accum, Wn, bn, out + (size_t)n * 64, n, 64);  // h_neighbor
}

// round 9
// speedup vs baseline: 2.1145x; 1.0870x over previous
#include <cuda_runtime.h>
#include <cstdint>

// Fixed dims: D=128, H=4, C=32, OUT=64. N,E from in_sizes.
#define MAXN 50048
#define MAXETOT 850048   // E + N self loops

// ---------------- scratch (device globals; allocation-free) ----------------
__device__ __align__(16) float g_xl   [(size_t)MAXN * 128];   // projected features
__device__ __align__(16) float g_accum[(size_t)MAXN * 128];   // layer output h0 / h1
__device__ __align__(16) float g_as   [(size_t)MAXN * 4];
__device__ __align__(16) float g_ad   [(size_t)MAXN * 4];
__device__ int g_deg   [MAXN];
__device__ int g_rowptr[MAXN + 1];
__device__ int g_cursor[MAXN];
__device__ int g_csrc  [MAXETOT];

__device__ __forceinline__ float lrelu(float x) { return x > 0.f ? x : 0.2f * x; }

// ================= CSR build (once per call; shared by both layers) =================
__global__ void k_initdeg(int* __restrict__ deg, int n) {
    int i = blockIdx.x * blockDim.x + threadIdx.x;
    if (i < n) deg[i] = 1;   // self loop
}
__global__ void k_count(const int* __restrict__ dst, int E, int* __restrict__ deg) {
    int e = blockIdx.x * blockDim.x + threadIdx.x;
    if (e < E) atomicAdd(&deg[dst[e]], 1);
}
__global__ void k_scan(const int* __restrict__ deg, int* __restrict__ rowptr,
                       int* __restrict__ cursor, int n) {
    __shared__ int sums[1024];
    int tid = threadIdx.x;                      // 1024 threads
    int chunk = (n + 1023) / 1024;
    int beg = tid * chunk;
    int end = min(beg + chunk, n);
    int s = 0;
    for (int i = beg; i < end; i++) s += deg[i];
    sums[tid] = s;
    __syncthreads();
    for (int off = 1; off < 1024; off <<= 1) {  // Hillis-Steele inclusive scan
        int v = (tid >= off) ? sums[tid - off] : 0;
        __syncthreads();
        sums[tid] += v;
        __syncthreads();
    }
    int run = (tid == 0) ? 0 : sums[tid - 1];
    for (int i = beg; i < end; i++) {
        rowptr[i] = run;
        cursor[i] = run;
        run += deg[i];
    }
    if (end == n) rowptr[n] = run;
}
__global__ void k_fill(const int* __restrict__ src, const int* __restrict__ dst,
                       int E, int Etot, int* __restrict__ cursor, int* __restrict__ csrc) {
    int e = blockIdx.x * blockDim.x + threadIdx.x;
    if (e >= Etot) return;
    int s, d;
    if (e < E) { s = src[e]; d = dst[e]; } else { s = e - E; d = s; }
    int p = atomicAdd(&cursor[d], 1);
    csrc[p] = s;
}

// ================= TF32 tensor-core GEMM (3xTF32, fp32-grade accuracy) ==============
// C[n,M] = A[n,128] @ W[128,M] (+bias).  Block tile 128x64, 8 warps (4x2), warp 32x32.
__device__ __forceinline__ uint32_t f2tf32(float f) {
    uint32_t r; asm("cvt.rna.tf32.f32 %0, %1;" : "=r"(r) : "f"(f)); return r;
}
__device__ __forceinline__ void mma8(float* d, const uint32_t* a, const uint32_t* b) {
    asm volatile("mma.sync.aligned.m16n8k8.row.col.f32.tf32.tf32.f32 "
        "{%0,%1,%2,%3}, {%4,%5,%6,%7}, {%8,%9}, {%0,%1,%2,%3};"
        : "+f"(d[0]), "+f"(d[1]), "+f"(d[2]), "+f"(d[3])
        : "r"(a[0]), "r"(a[1]), "r"(a[2]), "r"(a[3]), "r"(b[0]), "r"(b[1]));
}

__global__ void __launch_bounds__(256)
k_gemm_mma(const float* __restrict__ A, const float* __restrict__ W,
           const float* __restrict__ bias, float* __restrict__ C, int n, int M) {
    __shared__ __align__(16) float As[128][36];   // stride 36: frag loads conflict-free
    __shared__ __align__(16) float Ws[32][72];    // stride 72: frag loads conflict-free
    const int tid = threadIdx.x, l = tid & 31, wid = tid >> 5;
    const int wr = wid >> 1, wc = wid & 1;        // 4 x 2 warp grid
    const int rowBase = blockIdx.y * 128, colBase = blockIdx.x * 64;
    float acc[2][4][4] = {};                      // [mtile][ntile][frag]

    for (int kt = 0; kt < 128; kt += 32) {
        // stage A chunk [128 x 32]
        #pragma unroll
        for (int j = 0; j < 4; j++) {
            int idx = tid + 256 * j;
            int r = idx >> 3, c4 = (idx & 7) * 4;
            float4 v = make_float4(0.f, 0.f, 0.f, 0.f);
            int gr = rowBase + r;
            if (gr < n) v = *(const float4*)&A[(size_t)gr * 128 + kt + c4];
            *(float4*)&As[r][c4] = v;
        }
        // stage W chunk [32 x 64]
        #pragma unroll
        for (int j = 0; j < 2; j++) {
            int idx = tid + 256 * j;
            int k = idx >> 4, c4 = (idx & 15) * 4;
            *(float4*)&Ws[k][c4] = *(const float4*)&W[(size_t)(kt + k) * M + colBase + c4];
        }
        __syncthreads();

        #pragma unroll
        for (int k8 = 0; k8 < 4; k8++) {
            const int k0 = k8 * 8;
            uint32_t ahi[2][4], alo[2][4], bhi[4][2], blo[4][2];
            #pragma unroll
            for (int t = 0; t < 2; t++) {          // A frags (m16n8k8 tf32 layout)
                int r0 = wr * 32 + t * 16 + (l >> 2);
                int c0 = k0 + (l & 3);
                float f[4] = { As[r0][c0], As[r0 + 8][c0],
                               As[r0][c0 + 4], As[r0 + 8][c0 + 4] };
                #pragma unroll
                for (int q = 0; q < 4; q++) {
                    ahi[t][q] = f2tf32(f[q]);
                    alo[t][q] = f2tf32(f[q] - __uint_as_float(ahi[t][q]));
                }
            }
            #pragma unroll
            for (int u = 0; u < 4; u++) {          // B frags
                int col = wc * 32 + u * 8 + (l >> 2);
                float f0 = Ws[k0 + (l & 3)][col];
                float f1 = Ws[k0 + 4 + (l & 3)][col];
                bhi[u][0] = f2tf32(f0); blo[u][0] = f2tf32(f0 - __uint_as_float(bhi[u][0]));
                bhi[u][1] = f2tf32(f1); blo[u][1] = f2tf32(f1 - __uint_as_float(bhi[u][1]));
            }
            #pragma unroll
            for (int t = 0; t < 2; t++)
                #pragma unroll
                for (int u = 0; u < 4; u++) {
                    mma8(acc[t][u], ahi[t], bhi[u]);   // hi*hi
                    mma8(acc[t][u], ahi[t], blo[u]);   // hi*lo
                    mma8(acc[t][u], alo[t], bhi[u]);   // lo*hi
                }
        }
        __syncthreads();
    }

    // epilogue
    #pragma unroll
    for (int t = 0; t < 2; t++) {
        int row0 = rowBase + wr * 32 + t * 16 + (l >> 2);
        #pragma unroll
        for (int u = 0; u < 4; u++) {
            int col0 = colBase + wc * 32 + u * 8 + (l & 3) * 2;
            float b0 = 0.f, b1 = 0.f;
            if (bias) { b0 = bias[col0]; b1 = bias[col0 + 1]; }
            if (row0 < n) {
                C[(size_t)row0 * M + col0]     = acc[t][u][0] + b0;
                C[(size_t)row0 * M + col0 + 1] = acc[t][u][1] + b1;
            }
            if (row0 + 8 < n) {
                C[(size_t)(row0 + 8) * M + col0]     = acc[t][u][2] + b0;
                C[(size_t)(row0 + 8) * M + col0 + 1] = acc[t][u][3] + b1;
            }
        }
    }
}

// ================= attention dot products =================
__global__ void __launch_bounds__(256)
k_att(const float* __restrict__ xl, const float* __restrict__ ws,
      const float* __restrict__ wd, float* __restrict__ as_,
      float* __restrict__ ad_, int n, int H) {
    int warp = (blockIdx.x * blockDim.x + threadIdx.x) >> 5;
    int l = threadIdx.x & 31;
    if (warp >= n) return;
    float4 xv = *(const float4*)&xl[(size_t)warp * 128 + l * 4];
    float4 sv = *(const float4*)&ws[l * 4];
    float4 dv = *(const float4*)&wd[l * 4];
    float ps = xv.x * sv.x + xv.y * sv.y + xv.z * sv.z + xv.w * sv.w;
    float pd = xv.x * dv.x + xv.y * dv.y + xv.z * dv.z + xv.w * dv.w;
    int width = 32 / H;
    for (int off = width >> 1; off > 0; off >>= 1) {
        ps += __shfl_xor_sync(0xffffffffu, ps, off, width);
        pd += __shfl_xor_sync(0xffffffffu, pd, off, width);
    }
    if ((l & (width - 1)) == 0) {
        as_[warp * H + l / width] = ps;
        ad_[warp * H + l / width] = pd;
    }
}

// ================= fused GAT aggregation: warp per dst node, online softmax =========
template <int H>
__global__ void __launch_bounds__(256)
k_agg(const int* __restrict__ rowptr, const int* __restrict__ csrc,
      const float* __restrict__ as_, const float* __restrict__ ad_,
      const float* __restrict__ xl, const float* __restrict__ bias,
      float* __restrict__ outh, int n) {
    int d = (blockIdx.x * blockDim.x + threadIdx.x) >> 5;
    if (d >= n) return;
    int l = threadIdx.x & 31;
    const int head = (H == 4) ? (l >> 3) : 0;
    float a_d = ad_[d * H + head];
    int i = rowptr[d];
    int end = rowptr[d + 1];
    float m = -1e30f, den = 0.f;
    float4 acc = make_float4(0.f, 0.f, 0.f, 0.f);

    int s = (i < end) ? csrc[i] : 0;         // index pipelined one ahead
    for (; i < end; i++) {
        int sc = s;
        if (i + 1 < end) s = csrc[i + 1];
        float a = lrelu(as_[sc * H + head] + a_d);
        float4 xv = *(const float4*)&xl[(size_t)sc * 128 + l * 4];
        float nm = fmaxf(m, a);
        float rs = __expf(m - nm);
        float ex = __expf(a - nm);
        den = den * rs + ex;
        acc.x = acc.x * rs + ex * xv.x;
        acc.y = acc.y * rs + ex * xv.y;
        acc.z = acc.z * rs + ex * xv.z;
        acc.w = acc.w * rs + ex * xv.w;
        m = nm;
    }
    float inv = 1.f / (den + 1e-16f);
    float4 b = *(const float4*)&bias[l * 4];
    float4 o;
    o.x = fmaxf(acc.x * inv + b.x, 0.f);
    o.y = fmaxf(acc.y * inv + b.y, 0.f);
    o.z = fmaxf(acc.z * inv + b.z, 0.f);
    o.w = fmaxf(acc.w * inv + b.w, 0.f);
    *(float4*)&outh[(size_t)d * 128 + l * 4] = o;
}

// ================= launch =================
extern "C" void kernel_launch(void* const* d_in, const int* in_sizes, int n_in,
                              void* d_out, int out_size) {
    const float* x    = (const float*)d_in[0];
    const int*   ei   = (const int*)d_in[1];    // int32 (JAX x64 disabled)
    const float* W0   = (const float*)d_in[2];
    const float* as0w = (const float*)d_in[3];
    const float* ad0w = (const float*)d_in[4];
    const float* b0   = (const float*)d_in[5];
    const float* W1   = (const float*)d_in[6];
    const float* as1w = (const float*)d_in[7];
    const float* ad1w = (const float*)d_in[8];
    const float* b1   = (const float*)d_in[9];
    const float* Wn   = (const float*)d_in[10];
    const float* bn   = (const float*)d_in[11];
    const float* We   = (const float*)d_in[12];
    const float* be   = (const float*)d_in[13];
    float* out = (float*)d_out;

    const int n    = in_sizes[0] / 128;
    const int E    = in_sizes[1] / 2;
    const int Etot = E + n;
    const int* src = ei;
    const int* dst = ei + E;

    float *xl, *accum, *as_, *ad_;
    int *deg, *rowptr, *cursor, *csrc;
    cudaGetSymbolAddress((void**)&xl,     g_xl);
    cudaGetSymbolAddress((void**)&accum,  g_accum);
    cudaGetSymbolAddress((void**)&as_,    g_as);
    cudaGetSymbolAddress((void**)&ad_,    g_ad);
    cudaGetSymbolAddress((void**)&deg,    g_deg);
    cudaGetSymbolAddress((void**)&rowptr, g_rowptr);
    cudaGetSymbolAddress((void**)&cursor, g_cursor);
    cudaGetSymbolAddress((void**)&csrc,   g_csrc);

    const int T = 256;
    dim3 mmaGrid128(2, (n + 127) / 128);
    dim3 mmaGrid64(1, (n + 127) / 128);
    int nBlocks    = (n + T - 1) / T;
    int eBlocks    = (E + T - 1) / T;
    int etBlocks   = (Etot + T - 1) / T;
    int warpBlocks = (n + 7) / 8;

    // ---- CSR build ----
    k_initdeg<<<nBlocks, T>>>(deg, n);
    k_count<<<eBlocks, T>>>(dst, E, deg);
    k_scan<<<1, 1024>>>(deg, rowptr, cursor, n);
    k_fill<<<etBlocks, T>>>(src, dst, E, Etot, cursor, csrc);

    // ---- layer 0 (H=4, C=32) ----
    k_gemm_mma<<<mmaGrid128, T>>>(x, W0, nullptr, xl, n, 128);
    k_att<<<warpBlocks, T>>>(xl, as0w, ad0w, as_, ad_, n, 4);
    k_agg<4><<<warpBlocks, T>>>(rowptr, csrc, as_, ad_, xl, b0, accum, n);   // accum := h0

    // ---- layer 1 (H=1, C=128) ----
    k_gemm_mma<<<mmaGrid128, T>>>(accum, W1, nullptr, xl, n, 128);           // xl := h0 @ W1
    k_att<<<warpBlocks, T>>>(xl, as1w, ad1w, as_, ad_, n, 1);
    k_agg<1><<<warpBlocks, T>>>(rowptr, csrc, as_, ad_, xl, b1, accum, n);   // accum := h1

    // ---- projections ----
    k_gemm_mma<<<mmaGrid64, T>>>(x,     We, be, out,                  n, 64);  // h_ego
    k_gemm_mma<<<mmaGrid64, T>>>(accum, Wn, bn, out + (size_t)n * 64, n, 64);  // h_neighbor
}

// round 11
// speedup vs baseline: 2.1859x; 1.0338x over previous
#include <cuda_runtime.h>
#include <cstdint>

// Fixed dims: D=128, H=4, C=32, OUT=64. N,E from in_sizes.
#define MAXN 50048
#define MAXETOT 850048   // E + N self loops

// ---------------- scratch (device globals; allocation-free) ----------------
__device__ __align__(16) float g_xl   [(size_t)MAXN * 128];   // projected features
__device__ __align__(16) float g_accum[(size_t)MAXN * 128];   // layer output h0 / h1
__device__ __align__(16) float g_as   [(size_t)MAXN * 4];     // layer0 att dots (H=4)
__device__ __align__(16) float g_ad   [(size_t)MAXN * 4];
__device__ __align__(16) float g_as2  [MAXN];                 // layer1 att dots (H=1)
__device__ __align__(16) float g_ad2  [MAXN];
__device__ int g_deg   [MAXN];
__device__ int g_rowptr[MAXN + 1];
__device__ int g_cursor[MAXN];
__device__ int g_csrc  [MAXETOT];

__device__ __forceinline__ float lrelu(float x) { return x > 0.f ? x : 0.2f * x; }

// ================= CSR build (once per call; shared by both layers) =================
__global__ void k_initdeg(int* __restrict__ deg, float* __restrict__ as2,
                          float* __restrict__ ad2, int n) {
    int i = blockIdx.x * blockDim.x + threadIdx.x;
    if (i < n) { deg[i] = 1; as2[i] = 0.f; ad2[i] = 0.f; }   // self loop + zero H1 att
}
__global__ void k_count(const int* __restrict__ dst, int E, int* __restrict__ deg) {
    int e = blockIdx.x * blockDim.x + threadIdx.x;
    if (e < E) atomicAdd(&deg[dst[e]], 1);
}
__global__ void k_scan(const int* __restrict__ deg, int* __restrict__ rowptr,
                       int* __restrict__ cursor, int n) {
    __shared__ int sums[1024];
    int tid = threadIdx.x;                      // 1024 threads
    int chunk = (n + 1023) / 1024;
    int beg = tid * chunk;
    int end = min(beg + chunk, n);
    int s = 0;
    for (int i = beg; i < end; i++) s += deg[i];
    sums[tid] = s;
    __syncthreads();
    for (int off = 1; off < 1024; off <<= 1) {  // Hillis-Steele inclusive scan
        int v = (tid >= off) ? sums[tid - off] : 0;
        __syncthreads();
        sums[tid] += v;
        __syncthreads();
    }
    int run = (tid == 0) ? 0 : sums[tid - 1];
    for (int i = beg; i < end; i++) {
        rowptr[i] = run;
        cursor[i] = run;
        run += deg[i];
    }
    if (end == n) rowptr[n] = run;
}
__global__ void k_fill(const int* __restrict__ src, const int* __restrict__ dst,
                       int E, int Etot, int* __restrict__ cursor, int* __restrict__ csrc) {
    int e = blockIdx.x * blockDim.x + threadIdx.x;
    if (e >= Etot) return;
    int s, d;
    if (e < E) { s = src[e]; d = dst[e]; } else { s = e - E; d = s; }
    int p = atomicAdd(&cursor[d], 1);
    csrc[p] = s;
}

// ================= TF32 tensor-core GEMM (3xTF32) + fused attention epilogue ========
// C[n,M] = A[n,128] @ W[128,M] (+bias). Block tile 128x64, 8 warps (4x2), warp 32x32.
// attMode 0: none.  1: H=4 — warp's 32-col chunk == one head, direct store of as/ad.
// 2: H=1 — atomicAdd 32-col partials into pre-zeroed as/ad.
// blockIdx.z==1 selects the secondary (A2,W2,bias2,C2) problem (used to batch the
// two OUT=64 projections in a single launch).
__device__ __forceinline__ uint32_t f2tf32(float f) {
    uint32_t r; asm("cvt.rna.tf32.f32 %0, %1;" : "=r"(r) : "f"(f)); return r;
}
__device__ __forceinline__ void mma8(float* d, const uint32_t* a, const uint32_t* b) {
    asm volatile("mma.sync.aligned.m16n8k8.row.col.f32.tf32.tf32.f32 "
        "{%0,%1,%2,%3}, {%4,%5,%6,%7}, {%8,%9}, {%0,%1,%2,%3};"
        : "+f"(d[0]), "+f"(d[1]), "+f"(d[2]), "+f"(d[3])
        : "r"(a[0]), "r"(a[1]), "r"(a[2]), "r"(a[3]), "r"(b[0]), "r"(b[1]));
}

__global__ void __launch_bounds__(256)
k_gemm_mma(const float* __restrict__ A, const float* __restrict__ W,
           const float* __restrict__ bias, float* __restrict__ C, int n, int M,
           const float* __restrict__ attS, const float* __restrict__ attD,
           float* __restrict__ oAs, float* __restrict__ oAd, int attMode,
           const float* __restrict__ A2, const float* __restrict__ W2,
           const float* __restrict__ bias2, float* __restrict__ C2) {
    const float* Ap = A; const float* Wp = W; const float* bp = bias; float* Cp = C;
    if (blockIdx.z == 1) { Ap = A2; Wp = W2; bp = bias2; Cp = C2; }

    __shared__ __align__(16) float As[128][36];   // stride 36: conflict-free frag loads
    __shared__ __align__(16) float Ws[32][72];    // stride 72: conflict-free frag loads
    const int tid = threadIdx.x, l = tid & 31, wid = tid >> 5;
    const int wr = wid >> 1, wc = wid & 1;        // 4 x 2 warp grid
    const int rowBase = blockIdx.y * 128, colBase = blockIdx.x * 64;
    float acc[2][4][4] = {};                      // [mtile][ntile][frag]

    for (int kt = 0; kt < 128; kt += 32) {
        #pragma unroll
        for (int j = 0; j < 4; j++) {             // stage A chunk [128 x 32]
            int idx = tid + 256 * j;
            int r = idx >> 3, c4 = (idx & 7) * 4;
            float4 v = make_float4(0.f, 0.f, 0.f, 0.f);
            int gr = rowBase + r;
            if (gr < n) v = *(const float4*)&Ap[(size_t)gr * 128 + kt + c4];
            *(float4*)&As[r][c4] = v;
        }
        #pragma unroll
        for (int j = 0; j < 2; j++) {             // stage W chunk [32 x 64]
            int idx = tid + 256 * j;
            int k = idx >> 4, c4 = (idx & 15) * 4;
            *(float4*)&Ws[k][c4] = *(const float4*)&Wp[(size_t)(kt + k) * M + colBase + c4];
        }
        __syncthreads();

        #pragma unroll
        for (int k8 = 0; k8 < 4; k8++) {
            const int k0 = k8 * 8;
            uint32_t ahi[2][4], alo[2][4], bhi[4][2], blo[4][2];
            #pragma unroll
            for (int t = 0; t < 2; t++) {
                int r0 = wr * 32 + t * 16 + (l >> 2);
                int c0 = k0 + (l & 3);
                float f[4] = { As[r0][c0], As[r0 + 8][c0],
                               As[r0][c0 + 4], As[r0 + 8][c0 + 4] };
                #pragma unroll
                for (int q = 0; q < 4; q++) {
                    ahi[t][q] = f2tf32(f[q]);
                    alo[t][q] = f2tf32(f[q] - __uint_as_float(ahi[t][q]));
                }
            }
            #pragma unroll
            for (int u = 0; u < 4; u++) {
                int col = wc * 32 + u * 8 + (l >> 2);
                float f0 = Ws[k0 + (l & 3)][col];
                float f1 = Ws[k0 + 4 + (l & 3)][col];
                bhi[u][0] = f2tf32(f0); blo[u][0] = f2tf32(f0 - __uint_as_float(bhi[u][0]));
                bhi[u][1] = f2tf32(f1); blo[u][1] = f2tf32(f1 - __uint_as_float(bhi[u][1]));
            }
            #pragma unroll
            for (int t = 0; t < 2; t++)
                #pragma unroll
                for (int u = 0; u < 4; u++) {
                    mma8(acc[t][u], ahi[t], bhi[u]);
                    mma8(acc[t][u], ahi[t], blo[u]);
                    mma8(acc[t][u], alo[t], bhi[u]);
                }
        }
        __syncthreads();
    }

    // ---- C store ----
    #pragma unroll
    for (int t = 0; t < 2; t++) {
        int row0 = rowBase + wr * 32 + t * 16 + (l >> 2);
        #pragma unroll
        for (int u = 0; u < 4; u++) {
            int col0 = colBase + wc * 32 + u * 8 + (l & 3) * 2;
            float b0 = 0.f, b1 = 0.f;
            if (bp) { b0 = bp[col0]; b1 = bp[col0 + 1]; }
            if (row0 < n) {
                Cp[(size_t)row0 * M + col0]     = acc[t][u][0] + b0;
                Cp[(size_t)row0 * M + col0 + 1] = acc[t][u][1] + b1;
            }
            if (row0 + 8 < n) {
                Cp[(size_t)(row0 + 8) * M + col0]     = acc[t][u][2] + b0;
                Cp[(size_t)(row0 + 8) * M + col0 + 1] = acc[t][u][3] + b1;
            }
        }
    }

    // ---- fused attention dots over this warp's 32-col chunk ----
    if (attMode != 0) {
        const int head = blockIdx.x * 2 + wc;     // H=4: this chunk IS one head
        #pragma unroll
        for (int t = 0; t < 2; t++) {
            float pS[2] = {0.f, 0.f}, pD[2] = {0.f, 0.f};
            #pragma unroll
            for (int u = 0; u < 4; u++) {
                int cl = u * 8 + (l & 3) * 2;     // col within the 32-col chunk
                int cg = (attMode == 1) ? (head * 32 + cl) : (colBase + wc * 32 + cl);
                float wS0 = attS[cg], wS1 = attS[cg + 1];
                float wD0 = attD[cg], wD1 = attD[cg + 1];
                pS[0] += acc[t][u][0] * wS0 + acc[t][u][1] * wS1;
                pS[1] += acc[t][u][2] * wS0 + acc[t][u][3] * wS1;
                pD[0] += acc[t][u][0] * wD0 + acc[t][u][1] * wD1;
                pD[1] += acc[t][u][2] * wD0 + acc[t][u][3] * wD1;
            }
            #pragma unroll
            for (int off = 1; off <= 2; off <<= 1) {
                pS[0] += __shfl_xor_sync(0xffffffffu, pS[0], off);
                pS[1] += __shfl_xor_sync(0xffffffffu, pS[1], off);
                pD[0] += __shfl_xor_sync(0xffffffffu, pD[0], off);
                pD[1] += __shfl_xor_sync(0xffffffffu, pD[1], off);
            }
            if ((l & 3) == 0) {
                int row0 = rowBase + wr * 32 + t * 16 + (l >> 2);
                if (attMode == 1) {
                    if (row0 < n)     { oAs[row0 * 4 + head] = pS[0];       oAd[row0 * 4 + head] = pD[0]; }
                    if (row0 + 8 < n) { oAs[(row0 + 8) * 4 + head] = pS[1]; oAd[(row0 + 8) * 4 + head] = pD[1]; }
                } else {              // H=1: 4 partials per row across (bx, wc)
                    if (row0 < n)     { atomicAdd(&oAs[row0], pS[0]);     atomicAdd(&oAd[row0], pD[0]); }
                    if (row0 + 8 < n) { atomicAdd(&oAs[row0 + 8], pS[1]); atomicAdd(&oAd[row0 + 8], pD[1]); }
                }
            }
        }
    }
}

// ================= fused GAT aggregation: warp per dst node ========================
// Dual online-softmax accumulators (stride-2) halve the serial chain and double MLP.
template <int H>
__global__ void __launch_bounds__(256)
k_agg(const int* __restrict__ rowptr, const int* __restrict__ csrc,
      const float* __restrict__ as_, const float* __restrict__ ad_,
      const float* __restrict__ xl, const float* __restrict__ bias,
      float* __restrict__ outh, int n) {
    int d = (blockIdx.x * blockDim.x + threadIdx.x) >> 5;
    if (d >= n) return;
    int l = threadIdx.x & 31;
    const int head = (H == 4) ? (l >> 3) : 0;
    float a_d = ad_[d * H + head];
    int j = rowptr[d];
    const int end = rowptr[d + 1];

    float m0 = -1e30f, den0 = 0.f, m1 = -1e30f, den1 = 0.f;
    float4 ac0 = make_float4(0.f, 0.f, 0.f, 0.f);
    float4 ac1 = make_float4(0.f, 0.f, 0.f, 0.f);

    for (; j + 1 < end; j += 2) {
        int sA = csrc[j], sB = csrc[j + 1];
        float aA = lrelu(as_[sA * H + head] + a_d);
        float aB = lrelu(as_[sB * H + head] + a_d);
        float4 xA = *(const float4*)&xl[(size_t)sA * 128 + l * 4];
        float4 xB = *(const float4*)&xl[(size_t)sB * 128 + l * 4];
        {   // stream 0
            float nm = fmaxf(m0, aA);
            float rs = __expf(m0 - nm), ex = __expf(aA - nm);
            den0 = den0 * rs + ex;
            ac0.x = ac0.x * rs + ex * xA.x;
            ac0.y = ac0.y * rs + ex * xA.y;
            ac0.z = ac0.z * rs + ex * xA.z;
            ac0.w = ac0.w * rs + ex * xA.w;
            m0 = nm;
        }
        {   // stream 1
            float nm = fmaxf(m1, aB);
            float rs = __expf(m1 - nm), ex = __expf(aB - nm);
            den1 = den1 * rs + ex;
            ac1.x = ac1.x * rs + ex * xB.x;
            ac1.y = ac1.y * rs + ex * xB.y;
            ac1.z = ac1.z * rs + ex * xB.z;
            ac1.w = ac1.w * rs + ex * xB.w;
            m1 = nm;
        }
    }
    if (j < end) {   // odd tail -> stream 0
        int sA = csrc[j];
        float aA = lrelu(as_[sA * H + head] + a_d);
        float4 xA = *(const float4*)&xl[(size_t)sA * 128 + l * 4];
        float nm = fmaxf(m0, aA);
        float rs = __expf(m0 - nm), ex = __expf(aA - nm);
        den0 = den0 * rs + ex;
        ac0.x = ac0.x * rs + ex * xA.x;
        ac0.y = ac0.y * rs + ex * xA.y;
        ac0.z = ac0.z * rs + ex * xA.z;
        ac0.w = ac0.w * rs + ex * xA.w;
        m0 = nm;
    }
    // merge streams (deg >= 1 so m0 > -1e30; empty stream1 contributes exactly 0)
    float m = fmaxf(m0, m1);
    float r0 = __expf(m0 - m), r1 = __expf(m1 - m);
    float den = den0 * r0 + den1 * r1;
    float4 acc;
    acc.x = ac0.x * r0 + ac1.x * r1;
    acc.y = ac0.y * r0 + ac1.y * r1;
    acc.z = ac0.z * r0 + ac1.z * r1;
    acc.w = ac0.w * r0 + ac1.w * r1;

    float inv = 1.f / (den + 1e-16f);
    float4 b = *(const float4*)&bias[l * 4];
    float4 o;
    o.x = fmaxf(acc.x * inv + b.x, 0.f);
    o.y = fmaxf(acc.y * inv + b.y, 0.f);
    o.z = fmaxf(acc.z * inv + b.z, 0.f);
    o.w = fmaxf(acc.w * inv + b.w, 0.f);
    *(float4*)&outh[(size_t)d * 128 + l * 4] = o;
}

// ================= launch =================
extern "C" void kernel_launch(void* const* d_in, const int* in_sizes, int n_in,
                              void* d_out, int out_size) {
    const float* x    = (const float*)d_in[0];
    const int*   ei   = (const int*)d_in[1];    // int32 (JAX x64 disabled)
    const float* W0   = (const float*)d_in[2];
    const float* as0w = (const float*)d_in[3];
    const float* ad0w = (const float*)d_in[4];
    const float* b0   = (const float*)d_in[5];
    const float* W1   = (const float*)d_in[6];
    const float* as1w = (const float*)d_in[7];
    const float* ad1w = (const float*)d_in[8];
    const float* b1   = (const float*)d_in[9];
    const float* Wn   = (const float*)d_in[10];
    const float* bn   = (const float*)d_in[11];
    const float* We   = (const float*)d_in[12];
    const float* be   = (const float*)d_in[13];
    float* out = (float*)d_out;

    const int n    = in_sizes[0] / 128;
    const int E    = in_sizes[1] / 2;
    const int Etot = E + n;
    const int* src = ei;
    const int* dst = ei + E;

    float *xl, *accum, *as_, *ad_, *as2, *ad2;
    int *deg, *rowptr, *cursor, *csrc;
    cudaGetSymbolAddress((void**)&xl,     g_xl);
    cudaGetSymbolAddress((void**)&accum,  g_accum);
    cudaGetSymbolAddress((void**)&as_,    g_as);
    cudaGetSymbolAddress((void**)&ad_,    g_ad);
    cudaGetSymbolAddress((void**)&as2,    g_as2);
    cudaGetSymbolAddress((void**)&ad2,    g_ad2);
    cudaGetSymbolAddress((void**)&deg,    g_deg);
    cudaGetSymbolAddress((void**)&rowptr, g_rowptr);
    cudaGetSymbolAddress((void**)&cursor, g_cursor);
    cudaGetSymbolAddress((void**)&csrc,   g_csrc);

    const int T = 256;
    dim3 mmaGrid128(2, (n + 127) / 128, 1);
    dim3 mmaGridProj(1, (n + 127) / 128, 2);
    int nBlocks    = (n + T - 1) / T;
    int eBlocks    = (E + T - 1) / T;
    int etBlocks   = (Etot + T - 1) / T;
    int warpBlocks = (n + 7) / 8;

    // ---- CSR build (+ zero layer1 att buffers) ----
    k_initdeg<<<nBlocks, T>>>(deg, as2, ad2, n);
    k_count<<<eBlocks, T>>>(dst, E, deg);
    k_scan<<<1, 1024>>>(deg, rowptr, cursor, n);
    k_fill<<<etBlocks, T>>>(src, dst, E, Etot, cursor, csrc);

    // ---- layer 0 (H=4): GEMM + fused att dots ----
    k_gemm_mma<<<mmaGrid128, T>>>(x, W0, nullptr, xl, n, 128,
                                  as0w, ad0w, as_, ad_, 1,
                                  nullptr, nullptr, nullptr, nullptr);
    k_agg<4><<<warpBlocks, T>>>(rowptr, csrc, as_, ad_, xl, b0, accum, n);   // accum := h0

    // ---- layer 1 (H=1): GEMM + fused att dots (atomic partials into as2/ad2) ----
    k_gemm_mma<<<mmaGrid128, T>>>(accum, W1, nullptr, xl, n, 128,
                                  as1w, ad1w, as2, ad2, 2,
                                  nullptr, nullptr, nullptr, nullptr);
    k_agg<1><<<warpBlocks, T>>>(rowptr, csrc, as2, ad2, xl, b1, accum, n);   // accum := h1

    // ---- both projections in one launch (blockIdx.z selects problem) ----
    k_gemm_mma<<<mmaGridProj, T>>>(x, We, be, out, n, 64,
                                   nullptr, nullptr, nullptr, nullptr, 0,
                                   accum, Wn, bn, out + (size_t)n * 64);
}

// round 12
// speedup vs baseline: 2.2886x; 1.0470x over previous
#include <cuda_runtime.h>
#include <cstdint>

// Fixed dims: D=128, H=4, C=32, OUT=64. N,E from in_sizes.
#define MAXN 50048
#define MAXETOT 850048   // E + N self loops

// ---------------- scratch (device globals; allocation-free) ----------------
__device__ __align__(16) float g_xl   [(size_t)MAXN * 128];   // projected features
__device__ __align__(16) float g_accum[(size_t)MAXN * 128];   // layer output h0 / h1
__device__ __align__(16) float g_as   [(size_t)MAXN * 4];     // layer0 att dots (H=4)
__device__ __align__(16) float g_ad   [(size_t)MAXN * 4];
__device__ __align__(16) float g_as2  [MAXN];                 // layer1 att dots (H=1)
__device__ __align__(16) float g_ad2  [MAXN];
__device__ int g_deg   [MAXN];
__device__ int g_rowptr[MAXN + 1];
__device__ int g_cursor[MAXN];
__device__ int g_csrc  [MAXETOT];

__device__ __forceinline__ float lrelu(float x) { return x > 0.f ? x : 0.2f * x; }

// ================= CSR build (once per call; shared by both layers) =================
__global__ void k_initdeg(int* __restrict__ deg, float* __restrict__ as2,
                          float* __restrict__ ad2, int n) {
    int i = blockIdx.x * blockDim.x + threadIdx.x;
    if (i < n) { deg[i] = 1; as2[i] = 0.f; ad2[i] = 0.f; }   // self loop + zero H1 att
}
__global__ void k_count(const int* __restrict__ dst, int E, int* __restrict__ deg) {
    int e = blockIdx.x * blockDim.x + threadIdx.x;
    if (e < E) atomicAdd(&deg[dst[e]], 1);
}
__global__ void k_scan(const int* __restrict__ deg, int* __restrict__ rowptr,
                       int* __restrict__ cursor, int n) {
    __shared__ int sums[1024];
    int tid = threadIdx.x;                      // 1024 threads
    int chunk = (n + 1023) / 1024;
    int beg = tid * chunk;
    int end = min(beg + chunk, n);
    int s = 0;
    for (int i = beg; i < end; i++) s += deg[i];
    sums[tid] = s;
    __syncthreads();
    for (int off = 1; off < 1024; off <<= 1) {  // Hillis-Steele inclusive scan
        int v = (tid >= off) ? sums[tid - off] : 0;
        __syncthreads();
        sums[tid] += v;
        __syncthreads();
    }
    int run = (tid == 0) ? 0 : sums[tid - 1];
    for (int i = beg; i < end; i++) {
        rowptr[i] = run;
        cursor[i] = run;
        run += deg[i];
    }
    if (end == n) rowptr[n] = run;
}
__global__ void k_fill(const int* __restrict__ src, const int* __restrict__ dst,
                       int E, int Etot, int* __restrict__ cursor, int* __restrict__ csrc) {
    int e = blockIdx.x * blockDim.x + threadIdx.x;
    if (e >= Etot) return;
    int s, d;
    if (e < E) { s = src[e]; d = dst[e]; } else { s = e - E; d = s; }
    int p = atomicAdd(&cursor[d], 1);
    csrc[p] = s;
}

// ================= TF32 tensor-core GEMM (3xTF32) + fused attention epilogue ========
// C[n,M] = A[n,128] @ W[128,M] (+bias). Block tile 128x64, 8 warps (4x2), warp 32x32.
// attMode 0: none.  1: H=4 — warp's 32-col chunk == one head, direct store of as/ad.
// 2: H=1 — atomicAdd 32-col partials into pre-zeroed as/ad.
__device__ __forceinline__ uint32_t f2tf32(float f) {
    uint32_t r; asm("cvt.rna.tf32.f32 %0, %1;" : "=r"(r) : "f"(f)); return r;
}
__device__ __forceinline__ void mma8(float* d, const uint32_t* a, const uint32_t* b) {
    asm volatile("mma.sync.aligned.m16n8k8.row.col.f32.tf32.tf32.f32 "
        "{%0,%1,%2,%3}, {%4,%5,%6,%7}, {%8,%9}, {%0,%1,%2,%3};"
        : "+f"(d[0]), "+f"(d[1]), "+f"(d[2]), "+f"(d[3])
        : "r"(a[0]), "r"(a[1]), "r"(a[2]), "r"(a[3]), "r"(b[0]), "r"(b[1]));
}

__global__ void __launch_bounds__(256)
k_gemm_mma(const float* __restrict__ A, const float* __restrict__ W,
           const float* __restrict__ bias, float* __restrict__ C, int n, int M,
           const float* __restrict__ attS, const float* __restrict__ attD,
           float* __restrict__ oAs, float* __restrict__ oAd, int attMode) {
    __shared__ __align__(16) float As[128][36];   // stride 36: conflict-free frag loads
    __shared__ __align__(16) float Ws[32][72];    // stride 72: conflict-free frag loads
    const int tid = threadIdx.x, l = tid & 31, wid = tid >> 5;
    const int wr = wid >> 1, wc = wid & 1;        // 4 x 2 warp grid
    const int rowBase = blockIdx.y * 128, colBase = blockIdx.x * 64;
    float acc[2][4][4] = {};                      // [mtile][ntile][frag]

    for (int kt = 0; kt < 128; kt += 32) {
        #pragma unroll
        for (int j = 0; j < 4; j++) {             // stage A chunk [128 x 32]
            int idx = tid + 256 * j;
            int r = idx >> 3, c4 = (idx & 7) * 4;
            float4 v = make_float4(0.f, 0.f, 0.f, 0.f);
            int gr = rowBase + r;
            if (gr < n) v = *(const float4*)&A[(size_t)gr * 128 + kt + c4];
            *(float4*)&As[r][c4] = v;
        }
        #pragma unroll
        for (int j = 0; j < 2; j++) {             // stage W chunk [32 x 64]
            int idx = tid + 256 * j;
            int k = idx >> 4, c4 = (idx & 15) * 4;
            *(float4*)&Ws[k][c4] = *(const float4*)&W[(size_t)(kt + k) * M + colBase + c4];
        }
        __syncthreads();

        #pragma unroll
        for (int k8 = 0; k8 < 4; k8++) {
            const int k0 = k8 * 8;
            uint32_t ahi[2][4], alo[2][4], bhi[4][2], blo[4][2];
            #pragma unroll
            for (int t = 0; t < 2; t++) {
                int r0 = wr * 32 + t * 16 + (l >> 2);
                int c0 = k0 + (l & 3);
                float f[4] = { As[r0][c0], As[r0 + 8][c0],
                               As[r0][c0 + 4], As[r0 + 8][c0 + 4] };
                #pragma unroll
                for (int q = 0; q < 4; q++) {
                    ahi[t][q] = f2tf32(f[q]);
                    alo[t][q] = f2tf32(f[q] - __uint_as_float(ahi[t][q]));
                }
            }
            #pragma unroll
            for (int u = 0; u < 4; u++) {
                int col = wc * 32 + u * 8 + (l >> 2);
                float f0 = Ws[k0 + (l & 3)][col];
                float f1 = Ws[k0 + 4 + (l & 3)][col];
                bhi[u][0] = f2tf32(f0); blo[u][0] = f2tf32(f0 - __uint_as_float(bhi[u][0]));
                bhi[u][1] = f2tf32(f1); blo[u][1] = f2tf32(f1 - __uint_as_float(bhi[u][1]));
            }
            #pragma unroll
            for (int t = 0; t < 2; t++)
                #pragma unroll
                for (int u = 0; u < 4; u++) {
                    mma8(acc[t][u], ahi[t], bhi[u]);
                    mma8(acc[t][u], ahi[t], blo[u]);
                    mma8(acc[t][u], alo[t], bhi[u]);
                }
        }
        __syncthreads();
    }

    // ---- C store ----
    #pragma unroll
    for (int t = 0; t < 2; t++) {
        int row0 = rowBase + wr * 32 + t * 16 + (l >> 2);
        #pragma unroll
        for (int u = 0; u < 4; u++) {
            int col0 = colBase + wc * 32 + u * 8 + (l & 3) * 2;
            float b0 = 0.f, b1 = 0.f;
            if (bias) { b0 = bias[col0]; b1 = bias[col0 + 1]; }
            if (row0 < n) {
                C[(size_t)row0 * M + col0]     = acc[t][u][0] + b0;
                C[(size_t)row0 * M + col0 + 1] = acc[t][u][1] + b1;
            }
            if (row0 + 8 < n) {
                C[(size_t)(row0 + 8) * M + col0]     = acc[t][u][2] + b0;
                C[(size_t)(row0 + 8) * M + col0 + 1] = acc[t][u][3] + b1;
            }
        }
    }

    // ---- fused attention dots over this warp's 32-col chunk ----
    if (attMode != 0) {
        const int head = blockIdx.x * 2 + wc;     // H=4: this chunk IS one head
        #pragma unroll
        for (int t = 0; t < 2; t++) {
            float pS[2] = {0.f, 0.f}, pD[2] = {0.f, 0.f};
            #pragma unroll
            for (int u = 0; u < 4; u++) {
                int cl = u * 8 + (l & 3) * 2;     // col within the 32-col chunk
                int cg = (attMode == 1) ? (head * 32 + cl) : (colBase + wc * 32 + cl);
                float wS0 = attS[cg], wS1 = attS[cg + 1];
                float wD0 = attD[cg], wD1 = attD[cg + 1];
                pS[0] += acc[t][u][0] * wS0 + acc[t][u][1] * wS1;
                pS[1] += acc[t][u][2] * wS0 + acc[t][u][3] * wS1;
                pD[0] += acc[t][u][0] * wD0 + acc[t][u][1] * wD1;
                pD[1] += acc[t][u][2] * wD0 + acc[t][u][3] * wD1;
            }
            #pragma unroll
            for (int off = 1; off <= 2; off <<= 1) {
                pS[0] += __shfl_xor_sync(0xffffffffu, pS[0], off);
                pS[1] += __shfl_xor_sync(0xffffffffu, pS[1], off);
                pD[0] += __shfl_xor_sync(0xffffffffu, pD[0], off);
                pD[1] += __shfl_xor_sync(0xffffffffu, pD[1], off);
            }
            if ((l & 3) == 0) {
                int row0 = rowBase + wr * 32 + t * 16 + (l >> 2);
                if (attMode == 1) {
                    if (row0 < n)     { oAs[row0 * 4 + head] = pS[0];       oAd[row0 * 4 + head] = pD[0]; }
                    if (row0 + 8 < n) { oAs[(row0 + 8) * 4 + head] = pS[1]; oAd[(row0 + 8) * 4 + head] = pD[1]; }
                } else {              // H=1: 4 partials per row across (bx, wc)
                    if (row0 < n)     { atomicAdd(&oAs[row0], pS[0]);     atomicAdd(&oAd[row0], pD[0]); }
                    if (row0 + 8 < n) { atomicAdd(&oAs[row0 + 8], pS[1]); atomicAdd(&oAd[row0 + 8], pD[1]); }
                }
            }
        }
    }
}

// ================= fused GAT aggregation: warp per dst node ========================
// Dual online-softmax accumulators (stride-2) halve the serial chain and double MLP.
template <int H>
__global__ void __launch_bounds__(256)
k_agg(const int* __restrict__ rowptr, const int* __restrict__ csrc,
      const float* __restrict__ as_, const float* __restrict__ ad_,
      const float* __restrict__ xl, const float* __restrict__ bias,
      float* __restrict__ outh, int n) {
    int d = (blockIdx.x * blockDim.x + threadIdx.x) >> 5;
    if (d >= n) return;
    int l = threadIdx.x & 31;
    const int head = (H == 4) ? (l >> 3) : 0;
    float a_d = ad_[d * H + head];
    int j = rowptr[d];
    const int end = rowptr[d + 1];

    float m0 = -1e30f, den0 = 0.f, m1 = -1e30f, den1 = 0.f;
    float4 ac0 = make_float4(0.f, 0.f, 0.f, 0.f);
    float4 ac1 = make_float4(0.f, 0.f, 0.f, 0.f);

    for (; j + 1 < end; j += 2) {
        int sA = csrc[j], sB = csrc[j + 1];
        float aA = lrelu(as_[sA * H + head] + a_d);
        float aB = lrelu(as_[sB * H + head] + a_d);
        float4 xA = *(const float4*)&xl[(size_t)sA * 128 + l * 4];
        float4 xB = *(const float4*)&xl[(size_t)sB * 128 + l * 4];
        {   // stream 0
            float nm = fmaxf(m0, aA);
            float rs = __expf(m0 - nm), ex = __expf(aA - nm);
            den0 = den0 * rs + ex;
            ac0.x = ac0.x * rs + ex * xA.x;
            ac0.y = ac0.y * rs + ex * xA.y;
            ac0.z = ac0.z * rs + ex * xA.z;
            ac0.w = ac0.w * rs + ex * xA.w;
            m0 = nm;
        }
        {   // stream 1
            float nm = fmaxf(m1, aB);
            float rs = __expf(m1 - nm), ex = __expf(aB - nm);
            den1 = den1 * rs + ex;
            ac1.x = ac1.x * rs + ex * xB.x;
            ac1.y = ac1.y * rs + ex * xB.y;
            ac1.z = ac1.z * rs + ex * xB.z;
            ac1.w = ac1.w * rs + ex * xB.w;
            m1 = nm;
        }
    }
    if (j < end) {   // odd tail -> stream 0
        int sA = csrc[j];
        float aA = lrelu(as_[sA * H + head] + a_d);
        float4 xA = *(const float4*)&xl[(size_t)sA * 128 + l * 4];
        float nm = fmaxf(m0, aA);
        float rs = __expf(m0 - nm), ex = __expf(aA - nm);
        den0 = den0 * rs + ex;
        ac0.x = ac0.x * rs + ex * xA.x;
        ac0.y = ac0.y * rs + ex * xA.y;
        ac0.z = ac0.z * rs + ex * xA.z;
        ac0.w = ac0.w * rs + ex * xA.w;
        m0 = nm;
    }
    // merge streams (deg >= 1 so m0 > -1e30; empty stream1 contributes exactly 0)
    float m = fmaxf(m0, m1);
    float r0 = __expf(m0 - m), r1 = __expf(m1 - m);
    float den = den0 * r0 + den1 * r1;
    float4 acc;
    acc.x = ac0.x * r0 + ac1.x * r1;
    acc.y = ac0.y * r0 + ac1.y * r1;
    acc.z = ac0.z * r0 + ac1.z * r1;
    acc.w = ac0.w * r0 + ac1.w * r1;

    float inv = 1.f / (den + 1e-16f);
    float4 b = *(const float4*)&bias[l * 4];
    float4 o;
    o.x = fmaxf(acc.x * inv + b.x, 0.f);
    o.y = fmaxf(acc.y * inv + b.y, 0.f);
    o.z = fmaxf(acc.z * inv + b.z, 0.f);
    o.w = fmaxf(acc.w * inv + b.w, 0.f);
    *(float4*)&outh[(size_t)d * 128 + l * 4] = o;
}

// ================= launch (multi-stream DAG, graph-capture-safe fork/join) =========
extern "C" void kernel_launch(void* const* d_in, const int* in_sizes, int n_in,
                              void* d_out, int out_size) {
    const float* x    = (const float*)d_in[0];
    const int*   ei   = (const int*)d_in[1];    // int32 (JAX x64 disabled)
    const float* W0   = (const float*)d_in[2];
    const float* as0w = (const float*)d_in[3];
    const float* ad0w = (const float*)d_in[4];
    const float* b0   = (const float*)d_in[5];
    const float* W1   = (const float*)d_in[6];
    const float* as1w = (const float*)d_in[7];
    const float* ad1w = (const float*)d_in[8];
    const float* b1   = (const float*)d_in[9];
    const float* Wn   = (const float*)d_in[10];
    const float* bn   = (const float*)d_in[11];
    const float* We   = (const float*)d_in[12];
    const float* be   = (const float*)d_in[13];
    float* out = (float*)d_out;

    const int n    = in_sizes[0] / 128;
    const int E    = in_sizes[1] / 2;
    const int Etot = E + n;
    const int* src = ei;
    const int* dst = ei + E;

    float *xl, *accum, *as_, *ad_, *as2, *ad2;
    int *deg, *rowptr, *cursor, *csrc;
    cudaGetSymbolAddress((void**)&xl,     g_xl);
    cudaGetSymbolAddress((void**)&accum,  g_accum);
    cudaGetSymbolAddress((void**)&as_,    g_as);
    cudaGetSymbolAddress((void**)&ad_,    g_ad);
    cudaGetSymbolAddress((void**)&as2,    g_as2);
    cudaGetSymbolAddress((void**)&ad2,    g_ad2);
    cudaGetSymbolAddress((void**)&deg,    g_deg);
    cudaGetSymbolAddress((void**)&rowptr, g_rowptr);
    cudaGetSymbolAddress((void**)&cursor, g_cursor);
    cudaGetSymbolAddress((void**)&csrc,   g_csrc);

    // side streams + events (host-side resources; created once, reused — the GPU
    // work emitted per call is identical and deterministic)
    static cudaStream_t sCSR = nullptr, sEGO = nullptr;
    static cudaEvent_t  evFork = nullptr, evCSR = nullptr, evEGO = nullptr;
    if (!sCSR) {
        cudaStreamCreateWithFlags(&sCSR, cudaStreamNonBlocking);
        cudaStreamCreateWithFlags(&sEGO, cudaStreamNonBlocking);
        cudaEventCreateWithFlags(&evFork, cudaEventDisableTiming);
        cudaEventCreateWithFlags(&evCSR,  cudaEventDisableTiming);
        cudaEventCreateWithFlags(&evEGO,  cudaEventDisableTiming);
    }

    const int T = 256;
    dim3 mmaGrid128(2, (n + 127) / 128);
    dim3 mmaGrid64(1, (n + 127) / 128);
    int nBlocks    = (n + T - 1) / T;
    int eBlocks    = (E + T - 1) / T;
    int etBlocks   = (Etot + T - 1) / T;
    int warpBlocks = (n + 7) / 8;

    // fork side branches off the captured (default) stream
    cudaEventRecord(evFork, 0);
    cudaStreamWaitEvent(sCSR, evFork, 0);
    cudaStreamWaitEvent(sEGO, evFork, 0);

    // ---- branch CSR: build row pointers + column list (independent of GEMMs) ----
    k_initdeg<<<nBlocks, T, 0, sCSR>>>(deg, as2, ad2, n);
    k_count<<<eBlocks, T, 0, sCSR>>>(dst, E, deg);
    k_scan<<<1, 1024, 0, sCSR>>>(deg, rowptr, cursor, n);
    k_fill<<<etBlocks, T, 0, sCSR>>>(src, dst, E, Etot, cursor, csrc);
    cudaEventRecord(evCSR, sCSR);

    // ---- branch EGO: h_ego = x @ We + be (depends only on x) ----
    k_gemm_mma<<<mmaGrid64, T, 0, sEGO>>>(x, We, be, out, n, 64,
                                          nullptr, nullptr, nullptr, nullptr, 0);
    cudaEventRecord(evEGO, sEGO);

    // ---- main chain ----
    // layer 0 GEMM + fused att dots (runs concurrently with CSR + EGO branches)
    k_gemm_mma<<<mmaGrid128, T>>>(x, W0, nullptr, xl, n, 128,
                                  as0w, ad0w, as_, ad_, 1);
    cudaStreamWaitEvent(0, evCSR, 0);                  // join CSR before aggregation
    k_agg<4><<<warpBlocks, T>>>(rowptr, csrc, as_, ad_, xl, b0, accum, n);   // accum := h0

    // layer 1 GEMM + fused att dots (atomic partials into as2/ad2, zeroed on CSR branch)
    k_gemm_mma<<<mmaGrid128, T>>>(accum, W1, nullptr, xl, n, 128,
                                  as1w, ad1w, as2, ad2, 2);
    k_agg<1><<<warpBlocks, T>>>(rowptr, csrc, as2, ad2, xl, b1, accum, n);   // accum := h1

    // h_neighbor = h1 @ Wn + bn
    k_gemm_mma<<<mmaGrid64, T>>>(accum, Wn, bn, out + (size_t)n * 64, n, 64,
                                 nullptr, nullptr, nullptr, nullptr, 0);

    cudaStreamWaitEvent(0, evEGO, 0);                  // join EGO before graph end
}